// round 13
// baseline (speedup 1.0000x reference)
#include <cuda_runtime.h>
#include <math.h>
#include <stdint.h>

#define B_ 4
#define S_ 1024
#define D_ 512
#define H_ 8
#define E_ 64
#define BS_ (B_*S_)

// Scratch (device globals — no runtime allocation allowed)
__device__ float g_Q[H_*BS_*E_];     // [H][B*S][E]
__device__ float g_K[H_*BS_*E_];
__device__ float g_V[BS_*E_];
__device__ float g_M[BS_*E_];        // mean-over-heads accumulator
__device__ float g_G[B_*128*D_];     // final-GEMM output [512][512]

// ---------------------------------------------------------------------------
__device__ __forceinline__ uint32_t f2tf32(float x) {
    uint32_t r;
    asm("cvt.rna.tf32.f32 %0, %1;" : "=r"(r) : "f"(x));
    return r;
}
__device__ __forceinline__ void split_tf32(float x, uint32_t& hi, uint32_t& lo) {
    hi = f2tf32(x);
    lo = f2tf32(x - __uint_as_float(hi));
}

// D += A(16x8,row) * B(8x8,col)   tf32, fp32 accum
__device__ __forceinline__ void mma_tf32(float c[4],
                                         uint32_t a0, uint32_t a1, uint32_t a2, uint32_t a3,
                                         uint32_t b0, uint32_t b1) {
    asm volatile(
        "mma.sync.aligned.m16n8k8.row.col.f32.tf32.tf32.f32 "
        "{%0,%1,%2,%3}, {%4,%5,%6,%7}, {%8,%9}, {%0,%1,%2,%3};\n"
        : "+f"(c[0]), "+f"(c[1]), "+f"(c[2]), "+f"(c[3])
        : "r"(a0), "r"(a1), "r"(a2), "r"(a3), "r"(b0), "r"(b1));
}

// 3xTF32: acc += lo*hi + hi*lo + hi*hi  (~fp32 product precision)
__device__ __forceinline__ void mma3(float c[4],
                                     const uint32_t ah[4], const uint32_t al[4],
                                     uint32_t bh0, uint32_t bh1,
                                     uint32_t bl0, uint32_t bl1) {
    mma_tf32(c, al[0], al[1], al[2], al[3], bh0, bh1);
    mma_tf32(c, ah[0], ah[1], ah[2], ah[3], bl0, bl1);
    mma_tf32(c, ah[0], ah[1], ah[2], ah[3], bh0, bh1);
}

// ---------------------------------------------------------------------------
__global__ void zero_m_kernel() {
    int i = blockIdx.x * blockDim.x + threadIdx.x;
    int stride = gridDim.x * blockDim.x;
    for (; i < BS_*E_; i += stride) g_M[i] = 0.f;
}

// ---------------------------------------------------------------------------
// Batched projections via 3xTF32 MMA + register-prefetch (R12, PROVEN).
__global__ void proj_mma_kernel(const float* __restrict__ q, const float* __restrict__ k,
                                const float* __restrict__ v,
                                const float* __restrict__ Wq, const float* __restrict__ bq,
                                const float* __restrict__ Wk, const float* __restrict__ bk,
                                const float* __restrict__ Wv, const float* __restrict__ bv) {
    const int p = blockIdx.y;
    const float* A; const float* W; const float* bias; float* out;
    if (p < 8)       { A = q; W = Wq + (size_t)p*D_*E_;     bias = bq + p*E_;     out = g_Q + (size_t)p*BS_*E_; }
    else if (p < 16) { A = k; W = Wk + (size_t)(p-8)*D_*E_; bias = bk + (p-8)*E_; out = g_K + (size_t)(p-8)*BS_*E_; }
    else             { A = v; W = Wv;                        bias = bv;            out = g_V; }

    __shared__ float As[64*36];
    __shared__ float Bs[32*68];

    const int tid  = threadIdx.x;
    const int lane = tid & 31;
    const int warp = tid >> 5;
    const int wm = warp >> 1, wn = warp & 1;
    const int grp = lane >> 2, qid = lane & 3;
    const int m0 = blockIdx.x * 64;

    const int ar[4] = { (tid      ) >> 3, (tid + 128) >> 3, (tid + 256) >> 3, (tid + 384) >> 3 };
    const int ac[4] = { ((tid      ) & 7)*4, ((tid + 128) & 7)*4, ((tid + 256) & 7)*4, ((tid + 384) & 7)*4 };
    const int br[4] = { (tid      ) >> 4, (tid + 128) >> 4, (tid + 256) >> 4, (tid + 384) >> 4 };
    const int bc[4] = { ((tid      ) & 15)*4, ((tid + 128) & 15)*4, ((tid + 256) & 15)*4, ((tid + 384) & 15)*4 };

    float4 a_pre[4], b_pre[4];
    #pragma unroll
    for (int t = 0; t < 4; t++) {
        a_pre[t] = *(const float4*)&A[(size_t)(m0 + ar[t])*D_ + ac[t]];
        b_pre[t] = *(const float4*)&W[(size_t)br[t]*E_ + bc[t]];
    }

    float acc[2][4][4] = {};

    for (int k0 = 0; k0 < D_; k0 += 32) {
        #pragma unroll
        for (int t = 0; t < 4; t++) {
            *(float4*)&As[ar[t]*36 + ac[t]] = a_pre[t];
            *(float4*)&Bs[br[t]*68 + bc[t]] = b_pre[t];
        }
        if (k0 + 32 < D_) {
            #pragma unroll
            for (int t = 0; t < 4; t++) {
                a_pre[t] = *(const float4*)&A[(size_t)(m0 + ar[t])*D_ + k0 + 32 + ac[t]];
                b_pre[t] = *(const float4*)&W[(size_t)(k0 + 32 + br[t])*E_ + bc[t]];
            }
        }
        __syncthreads();

        #pragma unroll
        for (int ks = 0; ks < 4; ks++) {
            uint32_t ah[2][4], al[2][4];
            #pragma unroll
            for (int i = 0; i < 2; i++) {
                int row = wm*32 + i*16;
                split_tf32(As[(row+grp  )*36 + ks*8 + qid    ], ah[i][0], al[i][0]);
                split_tf32(As[(row+grp+8)*36 + ks*8 + qid    ], ah[i][1], al[i][1]);
                split_tf32(As[(row+grp  )*36 + ks*8 + qid + 4], ah[i][2], al[i][2]);
                split_tf32(As[(row+grp+8)*36 + ks*8 + qid + 4], ah[i][3], al[i][3]);
            }
            #pragma unroll
            for (int j = 0; j < 4; j++) {
                int col = wn*32 + j*8;
                uint32_t bh0, bl0, bh1, bl1;
                split_tf32(Bs[(ks*8 + qid    )*68 + col + grp], bh0, bl0);
                split_tf32(Bs[(ks*8 + qid + 4)*68 + col + grp], bh1, bl1);
                mma3(acc[0][j], ah[0], al[0], bh0, bh1, bl0, bl1);
                mma3(acc[1][j], ah[1], al[1], bh0, bh1, bl0, bl1);
            }
        }
        __syncthreads();
    }

    #pragma unroll
    for (int i = 0; i < 2; i++) {
        int row0 = m0 + wm*32 + i*16 + grp;
        #pragma unroll
        for (int j = 0; j < 4; j++) {
            int col0 = wn*32 + j*8 + qid*2;
            out[(size_t)row0*E_     + col0    ] = acc[i][j][0] + bias[col0    ];
            out[(size_t)row0*E_     + col0 + 1] = acc[i][j][1] + bias[col0 + 1];
            out[(size_t)(row0+8)*E_ + col0    ] = acc[i][j][2] + bias[col0    ];
            out[(size_t)(row0+8)*E_ + col0 + 1] = acc[i][j][3] + bias[col0 + 1];
        }
    }
}

// ---------------------------------------------------------------------------
// Full-MMA flash attention, BM=128 Q-tile: 8 warps, each owns 16 q-rows x
// all 64 key-cols (jn 0..7). Per-output fixed costs (K/V gmem+smem+convert,
// barriers, Q-splits, loop overhead) HALVED vs BM=64. R12 numerics.
// K/V register prefetch retained. Heavy tiles first (qt reversed).
__global__ void __launch_bounds__(256, 1) attn_kernel() {
    const int qt = (int)gridDim.x - 1 - (int)blockIdx.x;   // 0..7 (128-row tiles)
    const int b = blockIdx.y, h = blockIdx.z;
    extern __shared__ float sm[];
    float*    Qs  = sm;                      // 128*68 [q][e] fp32
    float*    Kt  = Qs + 128*68;             // 64*68  [e][key] fp32
    uint32_t* VsU = (uint32_t*)(Kt + 64*68); // 64*68  [key][e] tf32 bits
    float*    Ss  = (float*)(VsU + 64*68);   // 128*68 scores fp32 -> P tf32 bits
    uint32_t* SsU = (uint32_t*)Ss;
    float* m_sh = Ss + 128*68;               // 128
    float* l_sh = m_sh + 128;                // 128
    float* c_sh = l_sh + 128;                // 128

    const int tid  = threadIdx.x;
    const int lane = tid & 31;
    const int warp = tid >> 5;                   // 0..7 = wm
    const int grp = lane >> 2, qid = lane & 3;
    const int r0 = warp*16 + grp;                // C rows: r0, r0+8 (0..127)

    const float* Qp = g_Q + (((size_t)h*B_ + b)*S_ + (size_t)qt*128)*E_;
    const float* Kp = g_K + ((size_t)h*B_ + b)*S_*E_;
    const float* Vp = g_V + (size_t)b*S_*E_;

    const int lr = tid >> 4;            // 0..15
    const int lc = (tid & 15) * 4;      // col base

    // Q: 128x64, 8 float4 per thread
    #pragma unroll
    for (int t = 0; t < 8; t++) {
        int r = lr + t*16;
        *(float4*)&Qs[r*68 + lc] = *(const float4*)&Qp[(size_t)r*64 + lc];
    }
    if (tid < 128) { m_sh[tid] = -1e30f; l_sh[tid] = 0.f; }

    // prefetch K/V tile 0
    float4 kv_pre[4], vv_pre[4];
    #pragma unroll
    for (int t = 0; t < 4; t++) {
        int r = lr + t*16;
        kv_pre[t] = *(const float4*)&Kp[(size_t)r*64 + lc];
        vv_pre[t] = *(const float4*)&Vp[(size_t)r*64 + lc];
    }

    float acc_o[8][4] = {};                      // PV accumulator (C layout)
    const int jmax = 2*qt + 2;

    for (int j = 0; j < jmax; j++) {
        __syncthreads();   // prev reads done; Qs/init visible on iter 0
        #pragma unroll
        for (int t = 0; t < 4; t++) {
            int r = lr + t*16;                   // key row; lc = e base
            float4 kv = kv_pre[t];
            Kt[(lc+0)*68 + r] = kv.x;            // transpose: [e][key]
            Kt[(lc+1)*68 + r] = kv.y;
            Kt[(lc+2)*68 + r] = kv.z;
            Kt[(lc+3)*68 + r] = kv.w;
            float4 vv = vv_pre[t];
            VsU[r*68 + lc + 0] = f2tf32(vv.x);
            VsU[r*68 + lc + 1] = f2tf32(vv.y);
            VsU[r*68 + lc + 2] = f2tf32(vv.z);
            VsU[r*68 + lc + 3] = f2tf32(vv.w);
        }
        if (j + 1 < jmax) {
            #pragma unroll
            for (int t = 0; t < 4; t++) {
                int r = lr + t*16;
                kv_pre[t] = *(const float4*)&Kp[(size_t)((j+1)*64 + r)*64 + lc];
                vv_pre[t] = *(const float4*)&Vp[(size_t)((j+1)*64 + r)*64 + lc];
            }
        }
        __syncthreads();

        // ---- S = Q @ K^T via 3xTF32 MMA (8 jn tiles) ----
        float acc_s[8][4];
        #pragma unroll
        for (int jn = 0; jn < 8; jn++) { acc_s[jn][0]=0.f; acc_s[jn][1]=0.f; acc_s[jn][2]=0.f; acc_s[jn][3]=0.f; }
        #pragma unroll
        for (int ks = 0; ks < 8; ks++) {
            uint32_t ah[4], al[4];
            split_tf32(Qs[(r0    )*68 + ks*8 + qid    ], ah[0], al[0]);
            split_tf32(Qs[(r0 + 8)*68 + ks*8 + qid    ], ah[1], al[1]);
            split_tf32(Qs[(r0    )*68 + ks*8 + qid + 4], ah[2], al[2]);
            split_tf32(Qs[(r0 + 8)*68 + ks*8 + qid + 4], ah[3], al[3]);
            #pragma unroll
            for (int jn = 0; jn < 8; jn++) {
                int col = jn*8;
                uint32_t bh0, bl0, bh1, bl1;
                split_tf32(Kt[(ks*8 + qid    )*68 + col + grp], bh0, bl0);
                split_tf32(Kt[(ks*8 + qid + 4)*68 + col + grp], bh1, bl1);
                mma3(acc_s[jn], ah, al, bh0, bh1, bl0, bl1);
            }
        }
        // mask: key global (j*64 + c) vs row global (qt*128 + r)
        const bool diag = (j >= 2*qt);
        const int off = diag ? (j - 2*qt)*64 : 0;
        #pragma unroll
        for (int jn = 0; jn < 8; jn++) {
            int c0 = jn*8 + qid*2;
            float v0 = acc_s[jn][0] * 0.125f;
            float v1 = acc_s[jn][1] * 0.125f;
            float v2 = acc_s[jn][2] * 0.125f;
            float v3 = acc_s[jn][3] * 0.125f;
            if (diag) {
                if (off + c0     > r0    ) v0 = -1e30f;
                if (off + c0 + 1 > r0    ) v1 = -1e30f;
                if (off + c0     > r0 + 8) v2 = -1e30f;
                if (off + c0 + 1 > r0 + 8) v3 = -1e30f;
            }
            Ss[(r0    )*68 + c0    ] = v0;
            Ss[(r0    )*68 + c0 + 1] = v1;
            Ss[(r0 + 8)*68 + c0    ] = v2;
            Ss[(r0 + 8)*68 + c0 + 1] = v3;
        }
        __syncthreads();

        // ---- online softmax: 2 threads/row (128 rows), shfl combine ----
        {
            const int row  = tid >> 1;
            const int part = tid & 1;
            const int base = row*68 + part*32;
            float mold = m_sh[row];
            float mx = -1e30f;
            #pragma unroll
            for (int c = 0; c < 32; c++) mx = fmaxf(mx, Ss[base + c]);
            mx = fmaxf(mx, __shfl_xor_sync(0xffffffffu, mx, 1));
            mx = fmaxf(mx, mold);
            float sum = 0.f;
            #pragma unroll
            for (int c = 0; c < 32; c++) {
                float pv = __expf(Ss[base + c] - mx);
                sum += pv;
                SsU[base + c] = f2tf32(pv);
            }
            sum += __shfl_xor_sync(0xffffffffu, sum, 1);
            if (part == 0) {
                float corr = __expf(mold - mx);
                l_sh[row] = l_sh[row]*corr + sum;
                m_sh[row] = mx;
                c_sh[row] = corr;
            }
        }
        __syncthreads();

        // ---- O = O*corr + P @ V via single-pass TF32 MMA ----
        {
            float cA = c_sh[r0], cB = c_sh[r0 + 8];
            #pragma unroll
            for (int jn = 0; jn < 8; jn++) {
                acc_o[jn][0] *= cA; acc_o[jn][1] *= cA;
                acc_o[jn][2] *= cB; acc_o[jn][3] *= cB;
            }
            #pragma unroll
            for (int ks = 0; ks < 8; ks++) {
                uint32_t a0 = SsU[(r0    )*68 + ks*8 + qid    ];
                uint32_t a1 = SsU[(r0 + 8)*68 + ks*8 + qid    ];
                uint32_t a2 = SsU[(r0    )*68 + ks*8 + qid + 4];
                uint32_t a3 = SsU[(r0 + 8)*68 + ks*8 + qid + 4];
                #pragma unroll
                for (int jn = 0; jn < 8; jn++) {
                    int col = jn*8;
                    uint32_t b0 = VsU[(ks*8 + qid    )*68 + col + grp];
                    uint32_t b1 = VsU[(ks*8 + qid + 4)*68 + col + grp];
                    mma_tf32(acc_o[jn], a0, a1, a2, a3, b0, b1);
                }
            }
        }
    }
    __syncthreads();

    // ---- epilogue: MMA C layout, mean over heads via atomics ----
    {
        float invA = 1.f / (l_sh[r0    ] * (float)H_);
        float invB = 1.f / (l_sh[r0 + 8] * (float)H_);
        float* dst = &g_M[((size_t)b*S_ + qt*128)*E_];
        #pragma unroll
        for (int jn = 0; jn < 8; jn++) {
            int c0 = jn*8 + qid*2;
            atomicAdd(&dst[(size_t)(r0    )*E_ + c0    ], acc_o[jn][0]*invA);
            atomicAdd(&dst[(size_t)(r0    )*E_ + c0 + 1], acc_o[jn][1]*invA);
            atomicAdd(&dst[(size_t)(r0 + 8)*E_ + c0    ], acc_o[jn][2]*invB);
            atomicAdd(&dst[(size_t)(r0 + 8)*E_ + c0 + 1], acc_o[jn][3]*invB);
        }
    }
}

// ---------------------------------------------------------------------------
// Final linear: G = g_M[512,512] @ Wf[512,512] + register-prefetch (R12).
__global__ void gemm_g_kernel(const float* __restrict__ Wf) {
    __shared__ float As[64*36];
    __shared__ float Bs[32*68];
    const int tid  = threadIdx.x;
    const int lane = tid & 31;
    const int warp = tid >> 5;
    const int wm = warp >> 1, wn = warp & 1;
    const int grp = lane >> 2, qid = lane & 3;
    const int m0 = blockIdx.x * 64, n0 = blockIdx.y * 64;

    const int ar[4] = { (tid      ) >> 3, (tid + 128) >> 3, (tid + 256) >> 3, (tid + 384) >> 3 };
    const int ac[4] = { ((tid      ) & 7)*4, ((tid + 128) & 7)*4, ((tid + 256) & 7)*4, ((tid + 384) & 7)*4 };
    const int br[4] = { (tid      ) >> 4, (tid + 128) >> 4, (tid + 256) >> 4, (tid + 384) >> 4 };
    const int bc[4] = { ((tid      ) & 15)*4, ((tid + 128) & 15)*4, ((tid + 256) & 15)*4, ((tid + 384) & 15)*4 };

    float4 a_pre[4], b_pre[4];
    #pragma unroll
    for (int t = 0; t < 4; t++) {
        a_pre[t] = *(const float4*)&g_M[(size_t)(m0 + ar[t])*512 + ac[t]];
        b_pre[t] = *(const float4*)&Wf[(size_t)br[t]*512 + n0 + bc[t]];
    }

    float acc[2][4][4] = {};

    for (int k0 = 0; k0 < 512; k0 += 32) {
        #pragma unroll
        for (int t = 0; t < 4; t++) {
            *(float4*)&As[ar[t]*36 + ac[t]] = a_pre[t];
            *(float4*)&Bs[br[t]*68 + bc[t]] = b_pre[t];
        }
        if (k0 + 32 < 512) {
            #pragma unroll
            for (int t = 0; t < 4; t++) {
                a_pre[t] = *(const float4*)&g_M[(size_t)(m0 + ar[t])*512 + k0 + 32 + ac[t]];
                b_pre[t] = *(const float4*)&Wf[(size_t)(k0 + 32 + br[t])*512 + n0 + bc[t]];
            }
        }
        __syncthreads();

        #pragma unroll
        for (int ks = 0; ks < 4; ks++) {
            uint32_t ah[2][4], al[2][4];
            #pragma unroll
            for (int i = 0; i < 2; i++) {
                int row = wm*32 + i*16;
                split_tf32(As[(row+grp  )*36 + ks*8 + qid    ], ah[i][0], al[i][0]);
                split_tf32(As[(row+grp+8)*36 + ks*8 + qid    ], ah[i][1], al[i][1]);
                split_tf32(As[(row+grp  )*36 + ks*8 + qid + 4], ah[i][2], al[i][2]);
                split_tf32(As[(row+grp+8)*36 + ks*8 + qid + 4], ah[i][3], al[i][3]);
            }
            #pragma unroll
            for (int jn = 0; jn < 4; jn++) {
                int col = wn*32 + jn*8;
                uint32_t bh0, bl0, bh1, bl1;
                split_tf32(Bs[(ks*8 + qid    )*68 + col + grp], bh0, bl0);
                split_tf32(Bs[(ks*8 + qid + 4)*68 + col + grp], bh1, bl1);
                mma3(acc[0][jn], ah[0], al[0], bh0, bh1, bl0, bl1);
                mma3(acc[1][jn], ah[1], al[1], bh0, bh1, bl0, bl1);
            }
        }
        __syncthreads();
    }

    #pragma unroll
    for (int i = 0; i < 2; i++) {
        int row0 = m0 + wm*32 + i*16 + grp;
        #pragma unroll
        for (int jn = 0; jn < 4; jn++) {
            int col0 = n0 + wn*32 + jn*8 + qid*2;
            g_G[(size_t)row0*512     + col0    ] = acc[i][jn][0];
            g_G[(size_t)row0*512     + col0 + 1] = acc[i][jn][1];
            g_G[(size_t)(row0+8)*512 + col0    ] = acc[i][jn][2];
            g_G[(size_t)(row0+8)*512 + col0 + 1] = acc[i][jn][3];
        }
    }
}

// ---------------------------------------------------------------------------
__global__ void ln_kernel(const float* __restrict__ query, const float* __restrict__ bf,
                          const float* __restrict__ lnw, const float* __restrict__ lnb,
                          float* __restrict__ out) {
    const int row  = blockIdx.x;
    const int bb   = row >> 10;
    const int r128 = row & 127;
    const float* g    = g_G + ((size_t)bb*128 + r128)*D_;
    const float* qrow = query + (size_t)row*D_;
    const int tid = threadIdx.x;
    float x[4];
    float sum = 0.f;
    #pragma unroll
    for (int t = 0; t < 4; t++) {
        int c = tid + t*128;
        x[t] = g[c] + bf[c] + qrow[c];
        sum += x[t];
    }
    __shared__ float red[4];
    __shared__ float red2[4];
    #pragma unroll
    for (int off = 16; off; off >>= 1) sum += __shfl_xor_sync(0xffffffffu, sum, off);
    if ((tid & 31) == 0) red[tid >> 5] = sum;
    __syncthreads();
    float mean = (red[0]+red[1]+red[2]+red[3]) * (1.f/512.f);

    float sq = 0.f;
    #pragma unroll
    for (int t = 0; t < 4; t++) { float d = x[t] - mean; sq += d*d; }
    #pragma unroll
    for (int off = 16; off; off >>= 1) sq += __shfl_xor_sync(0xffffffffu, sq, off);
    if ((tid & 31) == 0) red2[tid >> 5] = sq;
    __syncthreads();
    float var_num = red2[0]+red2[1]+red2[2]+red2[3];
    float stdv = sqrtf(var_num * (1.f/511.f));
    float inv  = 1.f / (stdv + 1e-6f);
    #pragma unroll
    for (int t = 0; t < 4; t++) {
        int c = tid + t*128;
        out[(size_t)row*D_ + c] = lnw[c]*(x[t]-mean)*inv + lnb[c];
    }
}

// ---------------------------------------------------------------------------
extern "C" void kernel_launch(void* const* d_in, const int* in_sizes, int n_in,
                              void* d_out, int out_size) {
    const float* query = (const float*)d_in[0];
    const float* key   = (const float*)d_in[1];
    const float* value = (const float*)d_in[2];
    // d_in[3] = mask (tril, handled analytically)
    const float* Wq = (const float*)d_in[4];
    const float* bq = (const float*)d_in[5];
    const float* Wk = (const float*)d_in[6];
    const float* bk = (const float*)d_in[7];
    const float* Wv = (const float*)d_in[8];
    const float* bv = (const float*)d_in[9];
    const float* Wf = (const float*)d_in[10];
    const float* bf = (const float*)d_in[11];
    const float* lnw = (const float*)d_in[12];
    const float* lnb = (const float*)d_in[13];
    float* out = (float*)d_out;

    // attn smem: Qs 128*68 + Kt 64*68 + Vs 64*68 + Ss 128*68 + 3*128 floats
    const size_t attn_smem = (size_t)(128*68 + 64*68*2 + 128*68 + 3*128) * sizeof(float);
    cudaFuncSetAttribute(attn_kernel, cudaFuncAttributeMaxDynamicSharedMemorySize,
                         (int)attn_smem);

    zero_m_kernel<<<64, 256>>>();
    proj_mma_kernel<<<dim3(BS_/64, 17), 128>>>(query, key, value, Wq, bq, Wk, bk, Wv, bv);
    attn_kernel<<<dim3(S_/128, B_, H_), 256, attn_smem>>>();
    gemm_g_kernel<<<dim3(8, 8), 128>>>(Wf);
    ln_kernel<<<BS_, 128>>>(query, bf, lnw, lnb, out);
}

// round 14
// speedup vs baseline: 1.1454x; 1.1454x over previous
#include <cuda_runtime.h>
#include <math.h>
#include <stdint.h>

#define B_ 4
#define S_ 1024
#define D_ 512
#define H_ 8
#define E_ 64
#define BS_ (B_*S_)

// Scratch (device globals — no runtime allocation allowed)
__device__ float g_Q[H_*BS_*E_];     // [H][B*S][E]
__device__ float g_K[H_*BS_*E_];
__device__ float g_V[BS_*E_];
__device__ float g_M[BS_*E_];        // mean-over-heads accumulator
__device__ float g_G[B_*128*D_];     // final-GEMM output [512][512]

// ---------------------------------------------------------------------------
__device__ __forceinline__ uint32_t f2tf32(float x) {
    uint32_t r;
    asm("cvt.rna.tf32.f32 %0, %1;" : "=r"(r) : "f"(x));
    return r;
}
__device__ __forceinline__ void split_tf32(float x, uint32_t& hi, uint32_t& lo) {
    hi = f2tf32(x);
    lo = f2tf32(x - __uint_as_float(hi));
}

// D += A(16x8,row) * B(8x8,col)   tf32, fp32 accum
__device__ __forceinline__ void mma_tf32(float c[4],
                                         uint32_t a0, uint32_t a1, uint32_t a2, uint32_t a3,
                                         uint32_t b0, uint32_t b1) {
    asm volatile(
        "mma.sync.aligned.m16n8k8.row.col.f32.tf32.tf32.f32 "
        "{%0,%1,%2,%3}, {%4,%5,%6,%7}, {%8,%9}, {%0,%1,%2,%3};\n"
        : "+f"(c[0]), "+f"(c[1]), "+f"(c[2]), "+f"(c[3])
        : "r"(a0), "r"(a1), "r"(a2), "r"(a3), "r"(b0), "r"(b1));
}

// 3xTF32: acc += lo*hi + hi*lo + hi*hi  (~fp32 product precision)
__device__ __forceinline__ void mma3(float c[4],
                                     const uint32_t ah[4], const uint32_t al[4],
                                     uint32_t bh0, uint32_t bh1,
                                     uint32_t bl0, uint32_t bl1) {
    mma_tf32(c, al[0], al[1], al[2], al[3], bh0, bh1);
    mma_tf32(c, ah[0], ah[1], ah[2], ah[3], bl0, bl1);
    mma_tf32(c, ah[0], ah[1], ah[2], ah[3], bh0, bh1);
}

// ---------------------------------------------------------------------------
__global__ void zero_m_kernel() {
    int i = blockIdx.x * blockDim.x + threadIdx.x;
    int stride = gridDim.x * blockDim.x;
    for (; i < BS_*E_; i += stride) g_M[i] = 0.f;
}

// ---------------------------------------------------------------------------
// Batched projections via 3xTF32 MMA + register-prefetch (R12, PROVEN).
__global__ void proj_mma_kernel(const float* __restrict__ q, const float* __restrict__ k,
                                const float* __restrict__ v,
                                const float* __restrict__ Wq, const float* __restrict__ bq,
                                const float* __restrict__ Wk, const float* __restrict__ bk,
                                const float* __restrict__ Wv, const float* __restrict__ bv) {
    const int p = blockIdx.y;
    const float* A; const float* W; const float* bias; float* out;
    if (p < 8)       { A = q; W = Wq + (size_t)p*D_*E_;     bias = bq + p*E_;     out = g_Q + (size_t)p*BS_*E_; }
    else if (p < 16) { A = k; W = Wk + (size_t)(p-8)*D_*E_; bias = bk + (p-8)*E_; out = g_K + (size_t)(p-8)*BS_*E_; }
    else             { A = v; W = Wv;                        bias = bv;            out = g_V; }

    __shared__ float As[64*36];
    __shared__ float Bs[32*68];

    const int tid  = threadIdx.x;
    const int lane = tid & 31;
    const int warp = tid >> 5;
    const int wm = warp >> 1, wn = warp & 1;
    const int grp = lane >> 2, qid = lane & 3;
    const int m0 = blockIdx.x * 64;

    const int ar[4] = { (tid      ) >> 3, (tid + 128) >> 3, (tid + 256) >> 3, (tid + 384) >> 3 };
    const int ac[4] = { ((tid      ) & 7)*4, ((tid + 128) & 7)*4, ((tid + 256) & 7)*4, ((tid + 384) & 7)*4 };
    const int br[4] = { (tid      ) >> 4, (tid + 128) >> 4, (tid + 256) >> 4, (tid + 384) >> 4 };
    const int bc[4] = { ((tid      ) & 15)*4, ((tid + 128) & 15)*4, ((tid + 256) & 15)*4, ((tid + 384) & 15)*4 };

    float4 a_pre[4], b_pre[4];
    #pragma unroll
    for (int t = 0; t < 4; t++) {
        a_pre[t] = *(const float4*)&A[(size_t)(m0 + ar[t])*D_ + ac[t]];
        b_pre[t] = *(const float4*)&W[(size_t)br[t]*E_ + bc[t]];
    }

    float acc[2][4][4] = {};

    for (int k0 = 0; k0 < D_; k0 += 32) {
        #pragma unroll
        for (int t = 0; t < 4; t++) {
            *(float4*)&As[ar[t]*36 + ac[t]] = a_pre[t];
            *(float4*)&Bs[br[t]*68 + bc[t]] = b_pre[t];
        }
        if (k0 + 32 < D_) {
            #pragma unroll
            for (int t = 0; t < 4; t++) {
                a_pre[t] = *(const float4*)&A[(size_t)(m0 + ar[t])*D_ + k0 + 32 + ac[t]];
                b_pre[t] = *(const float4*)&W[(size_t)(k0 + 32 + br[t])*E_ + bc[t]];
            }
        }
        __syncthreads();

        #pragma unroll
        for (int ks = 0; ks < 4; ks++) {
            uint32_t ah[2][4], al[2][4];
            #pragma unroll
            for (int i = 0; i < 2; i++) {
                int row = wm*32 + i*16;
                split_tf32(As[(row+grp  )*36 + ks*8 + qid    ], ah[i][0], al[i][0]);
                split_tf32(As[(row+grp+8)*36 + ks*8 + qid    ], ah[i][1], al[i][1]);
                split_tf32(As[(row+grp  )*36 + ks*8 + qid + 4], ah[i][2], al[i][2]);
                split_tf32(As[(row+grp+8)*36 + ks*8 + qid + 4], ah[i][3], al[i][3]);
            }
            #pragma unroll
            for (int j = 0; j < 4; j++) {
                int col = wn*32 + j*8;
                uint32_t bh0, bl0, bh1, bl1;
                split_tf32(Bs[(ks*8 + qid    )*68 + col + grp], bh0, bl0);
                split_tf32(Bs[(ks*8 + qid + 4)*68 + col + grp], bh1, bl1);
                mma3(acc[0][j], ah[0], al[0], bh0, bh1, bl0, bl1);
                mma3(acc[1][j], ah[1], al[1], bh0, bh1, bl0, bl1);
            }
        }
        __syncthreads();
    }

    #pragma unroll
    for (int i = 0; i < 2; i++) {
        int row0 = m0 + wm*32 + i*16 + grp;
        #pragma unroll
        for (int j = 0; j < 4; j++) {
            int col0 = wn*32 + j*8 + qid*2;
            out[(size_t)row0*E_     + col0    ] = acc[i][j][0] + bias[col0    ];
            out[(size_t)row0*E_     + col0 + 1] = acc[i][j][1] + bias[col0 + 1];
            out[(size_t)(row0+8)*E_ + col0    ] = acc[i][j][2] + bias[col0    ];
            out[(size_t)(row0+8)*E_ + col0 + 1] = acc[i][j][3] + bias[col0 + 1];
        }
    }
}

// ---------------------------------------------------------------------------
// Full-MMA flash attention (R12 structure, BM=64, 3 CTAs/SM) with QK^T now
// SINGLE-PASS tf32: Q converted to tf32 bits once at load, K at tile load.
// Mainloop QK = pure LDS + 32 MMA (no cvt/fsub chains). PV single-pass (R10).
// K/V register prefetch (R12).
__global__ void attn_kernel() {
    const int qt = blockIdx.x, b = blockIdx.y, h = blockIdx.z;
    extern __shared__ float sm[];
    uint32_t* QsU = (uint32_t*)sm;           // 64*68 [q][e]   tf32 bits
    uint32_t* KtU = QsU + 64*68;             // 64*68 [e][key] tf32 bits
    uint32_t* VsU = KtU + 64*68;             // 64*68 [key][e] tf32 bits
    float*    Ss  = (float*)(VsU + 64*68);   // 64*68 scores fp32 -> P tf32 bits
    uint32_t* SsU = (uint32_t*)Ss;
    float* m_sh = Ss + 64*68;
    float* l_sh = m_sh + 64;
    float* c_sh = l_sh + 64;

    const int tid  = threadIdx.x;
    const int lane = tid & 31;
    const int warp = tid >> 5;                   // 0..7
    const int wm = warp >> 1, wn = warp & 1;
    const int grp = lane >> 2, qid = lane & 3;
    const int r0 = wm*16 + grp;                  // this thread's C rows: r0, r0+8

    const float* Qp = g_Q + (((size_t)h*B_ + b)*S_ + (size_t)qt*64)*E_;
    const float* Kp = g_K + ((size_t)h*B_ + b)*S_*E_;
    const float* Vp = g_V + (size_t)b*S_*E_;

    const int lr = tid >> 4;            // 0..15
    const int lc = (tid & 15) * 4;      // col base

    // Q: load + convert to tf32 bits ONCE
    #pragma unroll
    for (int t = 0; t < 4; t++) {
        int r = lr + t*16;
        float4 qv = *(const float4*)&Qp[(size_t)r*64 + lc];
        QsU[r*68 + lc + 0] = f2tf32(qv.x);
        QsU[r*68 + lc + 1] = f2tf32(qv.y);
        QsU[r*68 + lc + 2] = f2tf32(qv.z);
        QsU[r*68 + lc + 3] = f2tf32(qv.w);
    }
    if (tid < 64) { m_sh[tid] = -1e30f; l_sh[tid] = 0.f; }

    // prefetch K/V tile 0
    float4 kv_pre[4], vv_pre[4];
    #pragma unroll
    for (int t = 0; t < 4; t++) {
        int r = lr + t*16;
        kv_pre[t] = *(const float4*)&Kp[(size_t)r*64 + lc];
        vv_pre[t] = *(const float4*)&Vp[(size_t)r*64 + lc];
    }

    float acc_o[4][4] = {};                      // PV accumulator (C layout)

    for (int j = 0; j <= qt; j++) {
        __syncthreads();   // prev reads done; Qs/init visible on iter 0
        #pragma unroll
        for (int t = 0; t < 4; t++) {
            int r = lr + t*16;                   // key row; lc = e base
            float4 kv = kv_pre[t];
            KtU[(lc+0)*68 + r] = f2tf32(kv.x);   // transpose + convert
            KtU[(lc+1)*68 + r] = f2tf32(kv.y);
            KtU[(lc+2)*68 + r] = f2tf32(kv.z);
            KtU[(lc+3)*68 + r] = f2tf32(kv.w);
            float4 vv = vv_pre[t];
            VsU[r*68 + lc + 0] = f2tf32(vv.x);
            VsU[r*68 + lc + 1] = f2tf32(vv.y);
            VsU[r*68 + lc + 2] = f2tf32(vv.z);
            VsU[r*68 + lc + 3] = f2tf32(vv.w);
        }
        // issue next tile's loads NOW; they complete during compute below
        if (j < qt) {
            #pragma unroll
            for (int t = 0; t < 4; t++) {
                int r = lr + t*16;
                kv_pre[t] = *(const float4*)&Kp[(size_t)((j+1)*64 + r)*64 + lc];
                vv_pre[t] = *(const float4*)&Vp[(size_t)((j+1)*64 + r)*64 + lc];
            }
        }
        __syncthreads();

        // ---- S = Q @ K^T via single-pass TF32 MMA (bits direct from smem) ----
        float acc_s[4][4] = {};
        #pragma unroll
        for (int ks = 0; ks < 8; ks++) {
            uint32_t a0 = QsU[(r0    )*68 + ks*8 + qid    ];
            uint32_t a1 = QsU[(r0 + 8)*68 + ks*8 + qid    ];
            uint32_t a2 = QsU[(r0    )*68 + ks*8 + qid + 4];
            uint32_t a3 = QsU[(r0 + 8)*68 + ks*8 + qid + 4];
            #pragma unroll
            for (int jn = 0; jn < 4; jn++) {
                int col = wn*32 + jn*8;
                uint32_t b0 = KtU[(ks*8 + qid    )*68 + col + grp];
                uint32_t b1 = KtU[(ks*8 + qid + 4)*68 + col + grp];
                mma_tf32(acc_s[jn], a0, a1, a2, a3, b0, b1);
            }
        }
        const bool diag = (j == qt);
        #pragma unroll
        for (int jn = 0; jn < 4; jn++) {
            int c0 = wn*32 + jn*8 + qid*2;
            float v0 = acc_s[jn][0] * 0.125f;
            float v1 = acc_s[jn][1] * 0.125f;
            float v2 = acc_s[jn][2] * 0.125f;
            float v3 = acc_s[jn][3] * 0.125f;
            if (diag) {
                if (c0     > r0    ) v0 = -1e30f;
                if (c0 + 1 > r0    ) v1 = -1e30f;
                if (c0     > r0 + 8) v2 = -1e30f;
                if (c0 + 1 > r0 + 8) v3 = -1e30f;
            }
            Ss[(r0    )*68 + c0    ] = v0;
            Ss[(r0    )*68 + c0 + 1] = v1;
            Ss[(r0 + 8)*68 + c0    ] = v2;
            Ss[(r0 + 8)*68 + c0 + 1] = v3;
        }
        __syncthreads();

        // ---- online softmax: 4 threads/row, shfl combine; P -> tf32 bits ----
        {
            const int row  = tid >> 2;
            const int part = tid & 3;
            const int base = row*68 + part*16;
            float mold = m_sh[row];
            float mx = -1e30f;
            #pragma unroll
            for (int c = 0; c < 16; c++) mx = fmaxf(mx, Ss[base + c]);
            mx = fmaxf(mx, __shfl_xor_sync(0xffffffffu, mx, 1));
            mx = fmaxf(mx, __shfl_xor_sync(0xffffffffu, mx, 2));
            mx = fmaxf(mx, mold);
            float sum = 0.f;
            #pragma unroll
            for (int c = 0; c < 16; c++) {
                float pv = __expf(Ss[base + c] - mx);
                sum += pv;
                SsU[base + c] = f2tf32(pv);
            }
            sum += __shfl_xor_sync(0xffffffffu, sum, 1);
            sum += __shfl_xor_sync(0xffffffffu, sum, 2);
            if (part == 0) {
                float corr = __expf(mold - mx);
                l_sh[row] = l_sh[row]*corr + sum;
                m_sh[row] = mx;
                c_sh[row] = corr;
            }
        }
        __syncthreads();

        // ---- O = O*corr + P @ V via single-pass TF32 MMA ----
        {
            float cA = c_sh[r0], cB = c_sh[r0 + 8];
            #pragma unroll
            for (int jn = 0; jn < 4; jn++) {
                acc_o[jn][0] *= cA; acc_o[jn][1] *= cA;
                acc_o[jn][2] *= cB; acc_o[jn][3] *= cB;
            }
            #pragma unroll
            for (int ks = 0; ks < 8; ks++) {
                uint32_t a0 = SsU[(r0    )*68 + ks*8 + qid    ];
                uint32_t a1 = SsU[(r0 + 8)*68 + ks*8 + qid    ];
                uint32_t a2 = SsU[(r0    )*68 + ks*8 + qid + 4];
                uint32_t a3 = SsU[(r0 + 8)*68 + ks*8 + qid + 4];
                #pragma unroll
                for (int jn = 0; jn < 4; jn++) {
                    int col = wn*32 + jn*8;
                    uint32_t b0 = VsU[(ks*8 + qid    )*68 + col + grp];
                    uint32_t b1 = VsU[(ks*8 + qid + 4)*68 + col + grp];
                    mma_tf32(acc_o[jn], a0, a1, a2, a3, b0, b1);
                }
            }
        }
    }
    __syncthreads();

    // ---- epilogue: MMA C layout, mean over heads via atomics ----
    {
        float invA = 1.f / (l_sh[r0    ] * (float)H_);
        float invB = 1.f / (l_sh[r0 + 8] * (float)H_);
        float* dst = &g_M[((size_t)b*S_ + qt*64)*E_];
        #pragma unroll
        for (int jn = 0; jn < 4; jn++) {
            int c0 = wn*32 + jn*8 + qid*2;
            atomicAdd(&dst[(size_t)(r0    )*E_ + c0    ], acc_o[jn][0]*invA);
            atomicAdd(&dst[(size_t)(r0    )*E_ + c0 + 1], acc_o[jn][1]*invA);
            atomicAdd(&dst[(size_t)(r0 + 8)*E_ + c0    ], acc_o[jn][2]*invB);
            atomicAdd(&dst[(size_t)(r0 + 8)*E_ + c0 + 1], acc_o[jn][3]*invB);
        }
    }
}

// ---------------------------------------------------------------------------
// Final linear: G = g_M[512,512] @ Wf[512,512] + register-prefetch (R12).
__global__ void gemm_g_kernel(const float* __restrict__ Wf) {
    __shared__ float As[64*36];
    __shared__ float Bs[32*68];
    const int tid  = threadIdx.x;
    const int lane = tid & 31;
    const int warp = tid >> 5;
    const int wm = warp >> 1, wn = warp & 1;
    const int grp = lane >> 2, qid = lane & 3;
    const int m0 = blockIdx.x * 64, n0 = blockIdx.y * 64;

    const int ar[4] = { (tid      ) >> 3, (tid + 128) >> 3, (tid + 256) >> 3, (tid + 384) >> 3 };
    const int ac[4] = { ((tid      ) & 7)*4, ((tid + 128) & 7)*4, ((tid + 256) & 7)*4, ((tid + 384) & 7)*4 };
    const int br[4] = { (tid      ) >> 4, (tid + 128) >> 4, (tid + 256) >> 4, (tid + 384) >> 4 };
    const int bc[4] = { ((tid      ) & 15)*4, ((tid + 128) & 15)*4, ((tid + 256) & 15)*4, ((tid + 384) & 15)*4 };

    float4 a_pre[4], b_pre[4];
    #pragma unroll
    for (int t = 0; t < 4; t++) {
        a_pre[t] = *(const float4*)&g_M[(size_t)(m0 + ar[t])*512 + ac[t]];
        b_pre[t] = *(const float4*)&Wf[(size_t)br[t]*512 + n0 + bc[t]];
    }

    float acc[2][4][4] = {};

    for (int k0 = 0; k0 < 512; k0 += 32) {
        #pragma unroll
        for (int t = 0; t < 4; t++) {
            *(float4*)&As[ar[t]*36 + ac[t]] = a_pre[t];
            *(float4*)&Bs[br[t]*68 + bc[t]] = b_pre[t];
        }
        if (k0 + 32 < 512) {
            #pragma unroll
            for (int t = 0; t < 4; t++) {
                a_pre[t] = *(const float4*)&g_M[(size_t)(m0 + ar[t])*512 + k0 + 32 + ac[t]];
                b_pre[t] = *(const float4*)&Wf[(size_t)(k0 + 32 + br[t])*512 + n0 + bc[t]];
            }
        }
        __syncthreads();

        #pragma unroll
        for (int ks = 0; ks < 4; ks++) {
            uint32_t ah[2][4], al[2][4];
            #pragma unroll
            for (int i = 0; i < 2; i++) {
                int row = wm*32 + i*16;
                split_tf32(As[(row+grp  )*36 + ks*8 + qid    ], ah[i][0], al[i][0]);
                split_tf32(As[(row+grp+8)*36 + ks*8 + qid    ], ah[i][1], al[i][1]);
                split_tf32(As[(row+grp  )*36 + ks*8 + qid + 4], ah[i][2], al[i][2]);
                split_tf32(As[(row+grp+8)*36 + ks*8 + qid + 4], ah[i][3], al[i][3]);
            }
            #pragma unroll
            for (int jn = 0; jn < 4; jn++) {
                int col = wn*32 + jn*8;
                uint32_t bh0, bl0, bh1, bl1;
                split_tf32(Bs[(ks*8 + qid    )*68 + col + grp], bh0, bl0);
                split_tf32(Bs[(ks*8 + qid + 4)*68 + col + grp], bh1, bl1);
                mma3(acc[0][jn], ah[0], al[0], bh0, bh1, bl0, bl1);
                mma3(acc[1][jn], ah[1], al[1], bh0, bh1, bl0, bl1);
            }
        }
        __syncthreads();
    }

    #pragma unroll
    for (int i = 0; i < 2; i++) {
        int row0 = m0 + wm*32 + i*16 + grp;
        #pragma unroll
        for (int jn = 0; jn < 4; jn++) {
            int col0 = n0 + wn*32 + jn*8 + qid*2;
            g_G[(size_t)row0*512     + col0    ] = acc[i][jn][0];
            g_G[(size_t)row0*512     + col0 + 1] = acc[i][jn][1];
            g_G[(size_t)(row0+8)*512 + col0    ] = acc[i][jn][2];
            g_G[(size_t)(row0+8)*512 + col0 + 1] = acc[i][jn][3];
        }
    }
}

// ---------------------------------------------------------------------------
__global__ void ln_kernel(const float* __restrict__ query, const float* __restrict__ bf,
                          const float* __restrict__ lnw, const float* __restrict__ lnb,
                          float* __restrict__ out) {
    const int row  = blockIdx.x;
    const int bb   = row >> 10;
    const int r128 = row & 127;
    const float* g    = g_G + ((size_t)bb*128 + r128)*D_;
    const float* qrow = query + (size_t)row*D_;
    const int tid = threadIdx.x;
    float x[4];
    float sum = 0.f;
    #pragma unroll
    for (int t = 0; t < 4; t++) {
        int c = tid + t*128;
        x[t] = g[c] + bf[c] + qrow[c];
        sum += x[t];
    }
    __shared__ float red[4];
    __shared__ float red2[4];
    #pragma unroll
    for (int off = 16; off; off >>= 1) sum += __shfl_xor_sync(0xffffffffu, sum, off);
    if ((tid & 31) == 0) red[tid >> 5] = sum;
    __syncthreads();
    float mean = (red[0]+red[1]+red[2]+red[3]) * (1.f/512.f);

    float sq = 0.f;
    #pragma unroll
    for (int t = 0; t < 4; t++) { float d = x[t] - mean; sq += d*d; }
    #pragma unroll
    for (int off = 16; off; off >>= 1) sq += __shfl_xor_sync(0xffffffffu, sq, off);
    if ((tid & 31) == 0) red2[tid >> 5] = sq;
    __syncthreads();
    float var_num = red2[0]+red2[1]+red2[2]+red2[3];
    float stdv = sqrtf(var_num * (1.f/511.f));
    float inv  = 1.f / (stdv + 1e-6f);
    #pragma unroll
    for (int t = 0; t < 4; t++) {
        int c = tid + t*128;
        out[(size_t)row*D_ + c] = lnw[c]*(x[t]-mean)*inv + lnb[c];
    }
}

// ---------------------------------------------------------------------------
extern "C" void kernel_launch(void* const* d_in, const int* in_sizes, int n_in,
                              void* d_out, int out_size) {
    const float* query = (const float*)d_in[0];
    const float* key   = (const float*)d_in[1];
    const float* value = (const float*)d_in[2];
    // d_in[3] = mask (tril, handled analytically)
    const float* Wq = (const float*)d_in[4];
    const float* bq = (const float*)d_in[5];
    const float* Wk = (const float*)d_in[6];
    const float* bk = (const float*)d_in[7];
    const float* Wv = (const float*)d_in[8];
    const float* bv = (const float*)d_in[9];
    const float* Wf = (const float*)d_in[10];
    const float* bf = (const float*)d_in[11];
    const float* lnw = (const float*)d_in[12];
    const float* lnb = (const float*)d_in[13];
    float* out = (float*)d_out;

    // attn smem: 4 tiles of 64*68 + 3*64 floats = 70400 B (R12 layout)
    const size_t attn_smem = (size_t)(4*64*68 + 3*64) * sizeof(float);
    cudaFuncSetAttribute(attn_kernel, cudaFuncAttributeMaxDynamicSharedMemorySize,
                         (int)attn_smem);

    zero_m_kernel<<<64, 256>>>();
    proj_mma_kernel<<<dim3(BS_/64, 17), 128>>>(query, key, value, Wq, bq, Wk, bk, Wv, bv);
    attn_kernel<<<dim3(S_/64, B_, H_), 256, attn_smem>>>();
    gemm_g_kernel<<<dim3(8, 8), 128>>>(Wf);
    ln_kernel<<<BS_, 128>>>(query, bf, lnw, lnb, out);
}

// round 15
// speedup vs baseline: 1.4184x; 1.2383x over previous
#include <cuda_runtime.h>
#include <math.h>
#include <stdint.h>

#define B_ 4
#define S_ 1024
#define D_ 512
#define H_ 8
#define E_ 64
#define BS_ (B_*S_)

// Scratch (device globals — no runtime allocation allowed)
__device__ float g_Q[H_*BS_*E_];     // [H][B*S][E]
__device__ float g_K[H_*BS_*E_];
__device__ float g_V[BS_*E_];
__device__ float g_M[BS_*E_];        // mean-over-heads accumulator
__device__ float g_G[B_*128*D_];     // final-GEMM output [512][512]

// ---------------------------------------------------------------------------
__device__ __forceinline__ uint32_t f2tf32(float x) {
    uint32_t r;
    asm("cvt.rna.tf32.f32 %0, %1;" : "=r"(r) : "f"(x));
    return r;
}

// D += A(16x8,row) * B(8x8,col)   tf32, fp32 accum
__device__ __forceinline__ void mma_tf32(float c[4],
                                         uint32_t a0, uint32_t a1, uint32_t a2, uint32_t a3,
                                         uint32_t b0, uint32_t b1) {
    asm volatile(
        "mma.sync.aligned.m16n8k8.row.col.f32.tf32.tf32.f32 "
        "{%0,%1,%2,%3}, {%4,%5,%6,%7}, {%8,%9}, {%0,%1,%2,%3};\n"
        : "+f"(c[0]), "+f"(c[1]), "+f"(c[2]), "+f"(c[3])
        : "r"(a0), "r"(a1), "r"(a2), "r"(a3), "r"(b0), "r"(b1));
}

// ---------------------------------------------------------------------------
__global__ void zero_m_kernel() {
    int i = blockIdx.x * blockDim.x + threadIdx.x;
    int stride = gridDim.x * blockDim.x;
    for (; i < BS_*E_; i += stride) g_M[i] = 0.f;
}

// ---------------------------------------------------------------------------
// Batched projections, single-pass tf32: smem holds tf32 BITS (converted at
// the store stage), mainloop is pure LDS+MMA. Register prefetch (R12).
// p<8: Q head p; p<16: K; 16: V.
__global__ void proj_mma_kernel(const float* __restrict__ q, const float* __restrict__ k,
                                const float* __restrict__ v,
                                const float* __restrict__ Wq, const float* __restrict__ bq,
                                const float* __restrict__ Wk, const float* __restrict__ bk,
                                const float* __restrict__ Wv, const float* __restrict__ bv) {
    const int p = blockIdx.y;
    const float* A; const float* W; const float* bias; float* out;
    if (p < 8)       { A = q; W = Wq + (size_t)p*D_*E_;     bias = bq + p*E_;     out = g_Q + (size_t)p*BS_*E_; }
    else if (p < 16) { A = k; W = Wk + (size_t)(p-8)*D_*E_; bias = bk + (p-8)*E_; out = g_K + (size_t)(p-8)*BS_*E_; }
    else             { A = v; W = Wv;                        bias = bv;            out = g_V; }

    __shared__ uint32_t As[64*36];   // [row][k]  tf32 bits
    __shared__ uint32_t Bs[32*68];   // [k][n]    tf32 bits

    const int tid  = threadIdx.x;
    const int lane = tid & 31;
    const int warp = tid >> 5;
    const int wm = warp >> 1, wn = warp & 1;
    const int grp = lane >> 2, qid = lane & 3;
    const int m0 = blockIdx.x * 64;

    const int ar[4] = { (tid      ) >> 3, (tid + 128) >> 3, (tid + 256) >> 3, (tid + 384) >> 3 };
    const int ac[4] = { ((tid      ) & 7)*4, ((tid + 128) & 7)*4, ((tid + 256) & 7)*4, ((tid + 384) & 7)*4 };
    const int br[4] = { (tid      ) >> 4, (tid + 128) >> 4, (tid + 256) >> 4, (tid + 384) >> 4 };
    const int bc[4] = { ((tid      ) & 15)*4, ((tid + 128) & 15)*4, ((tid + 256) & 15)*4, ((tid + 384) & 15)*4 };

    float4 a_pre[4], b_pre[4];
    #pragma unroll
    for (int t = 0; t < 4; t++) {
        a_pre[t] = *(const float4*)&A[(size_t)(m0 + ar[t])*D_ + ac[t]];
        b_pre[t] = *(const float4*)&W[(size_t)br[t]*E_ + bc[t]];
    }

    float acc[2][4][4] = {};

    for (int k0 = 0; k0 < D_; k0 += 32) {
        #pragma unroll
        for (int t = 0; t < 4; t++) {
            float4 av = a_pre[t];
            As[ar[t]*36 + ac[t] + 0] = f2tf32(av.x);
            As[ar[t]*36 + ac[t] + 1] = f2tf32(av.y);
            As[ar[t]*36 + ac[t] + 2] = f2tf32(av.z);
            As[ar[t]*36 + ac[t] + 3] = f2tf32(av.w);
            float4 bvv = b_pre[t];
            Bs[br[t]*68 + bc[t] + 0] = f2tf32(bvv.x);
            Bs[br[t]*68 + bc[t] + 1] = f2tf32(bvv.y);
            Bs[br[t]*68 + bc[t] + 2] = f2tf32(bvv.z);
            Bs[br[t]*68 + bc[t] + 3] = f2tf32(bvv.w);
        }
        if (k0 + 32 < D_) {
            #pragma unroll
            for (int t = 0; t < 4; t++) {
                a_pre[t] = *(const float4*)&A[(size_t)(m0 + ar[t])*D_ + k0 + 32 + ac[t]];
                b_pre[t] = *(const float4*)&W[(size_t)(k0 + 32 + br[t])*E_ + bc[t]];
            }
        }
        __syncthreads();

        #pragma unroll
        for (int ks = 0; ks < 4; ks++) {
            uint32_t a[2][4];
            #pragma unroll
            for (int i = 0; i < 2; i++) {
                int row = wm*32 + i*16;
                a[i][0] = As[(row+grp  )*36 + ks*8 + qid    ];
                a[i][1] = As[(row+grp+8)*36 + ks*8 + qid    ];
                a[i][2] = As[(row+grp  )*36 + ks*8 + qid + 4];
                a[i][3] = As[(row+grp+8)*36 + ks*8 + qid + 4];
            }
            #pragma unroll
            for (int j = 0; j < 4; j++) {
                int col = wn*32 + j*8;
                uint32_t b0 = Bs[(ks*8 + qid    )*68 + col + grp];
                uint32_t b1 = Bs[(ks*8 + qid + 4)*68 + col + grp];
                mma_tf32(acc[0][j], a[0][0], a[0][1], a[0][2], a[0][3], b0, b1);
                mma_tf32(acc[1][j], a[1][0], a[1][1], a[1][2], a[1][3], b0, b1);
            }
        }
        __syncthreads();
    }

    #pragma unroll
    for (int i = 0; i < 2; i++) {
        int row0 = m0 + wm*32 + i*16 + grp;
        #pragma unroll
        for (int j = 0; j < 4; j++) {
            int col0 = wn*32 + j*8 + qid*2;
            out[(size_t)row0*E_     + col0    ] = acc[i][j][0] + bias[col0    ];
            out[(size_t)row0*E_     + col0 + 1] = acc[i][j][1] + bias[col0 + 1];
            out[(size_t)(row0+8)*E_ + col0    ] = acc[i][j][2] + bias[col0    ];
            out[(size_t)(row0+8)*E_ + col0 + 1] = acc[i][j][3] + bias[col0 + 1];
        }
    }
}

// ---------------------------------------------------------------------------
// Full-MMA flash attention, all single-pass tf32 (R14, PROVEN): Q/K/V/P as
// tf32 bits in smem, pure LDS+MMA mainloop, K/V register prefetch.
__global__ void attn_kernel() {
    const int qt = blockIdx.x, b = blockIdx.y, h = blockIdx.z;
    extern __shared__ float sm[];
    uint32_t* QsU = (uint32_t*)sm;           // 64*68 [q][e]   tf32 bits
    uint32_t* KtU = QsU + 64*68;             // 64*68 [e][key] tf32 bits
    uint32_t* VsU = KtU + 64*68;             // 64*68 [key][e] tf32 bits
    float*    Ss  = (float*)(VsU + 64*68);   // 64*68 scores fp32 -> P tf32 bits
    uint32_t* SsU = (uint32_t*)Ss;
    float* m_sh = Ss + 64*68;
    float* l_sh = m_sh + 64;
    float* c_sh = l_sh + 64;

    const int tid  = threadIdx.x;
    const int lane = tid & 31;
    const int warp = tid >> 5;                   // 0..7
    const int wm = warp >> 1, wn = warp & 1;
    const int grp = lane >> 2, qid = lane & 3;
    const int r0 = wm*16 + grp;                  // this thread's C rows: r0, r0+8

    const float* Qp = g_Q + (((size_t)h*B_ + b)*S_ + (size_t)qt*64)*E_;
    const float* Kp = g_K + ((size_t)h*B_ + b)*S_*E_;
    const float* Vp = g_V + (size_t)b*S_*E_;

    const int lr = tid >> 4;            // 0..15
    const int lc = (tid & 15) * 4;      // col base

    // Q: load + convert to tf32 bits ONCE
    #pragma unroll
    for (int t = 0; t < 4; t++) {
        int r = lr + t*16;
        float4 qv = *(const float4*)&Qp[(size_t)r*64 + lc];
        QsU[r*68 + lc + 0] = f2tf32(qv.x);
        QsU[r*68 + lc + 1] = f2tf32(qv.y);
        QsU[r*68 + lc + 2] = f2tf32(qv.z);
        QsU[r*68 + lc + 3] = f2tf32(qv.w);
    }
    if (tid < 64) { m_sh[tid] = -1e30f; l_sh[tid] = 0.f; }

    // prefetch K/V tile 0
    float4 kv_pre[4], vv_pre[4];
    #pragma unroll
    for (int t = 0; t < 4; t++) {
        int r = lr + t*16;
        kv_pre[t] = *(const float4*)&Kp[(size_t)r*64 + lc];
        vv_pre[t] = *(const float4*)&Vp[(size_t)r*64 + lc];
    }

    float acc_o[4][4] = {};                      // PV accumulator (C layout)

    for (int j = 0; j <= qt; j++) {
        __syncthreads();   // prev reads done; Qs/init visible on iter 0
        #pragma unroll
        for (int t = 0; t < 4; t++) {
            int r = lr + t*16;                   // key row; lc = e base
            float4 kv = kv_pre[t];
            KtU[(lc+0)*68 + r] = f2tf32(kv.x);   // transpose + convert
            KtU[(lc+1)*68 + r] = f2tf32(kv.y);
            KtU[(lc+2)*68 + r] = f2tf32(kv.z);
            KtU[(lc+3)*68 + r] = f2tf32(kv.w);
            float4 vv = vv_pre[t];
            VsU[r*68 + lc + 0] = f2tf32(vv.x);
            VsU[r*68 + lc + 1] = f2tf32(vv.y);
            VsU[r*68 + lc + 2] = f2tf32(vv.z);
            VsU[r*68 + lc + 3] = f2tf32(vv.w);
        }
        // issue next tile's loads NOW; they complete during compute below
        if (j < qt) {
            #pragma unroll
            for (int t = 0; t < 4; t++) {
                int r = lr + t*16;
                kv_pre[t] = *(const float4*)&Kp[(size_t)((j+1)*64 + r)*64 + lc];
                vv_pre[t] = *(const float4*)&Vp[(size_t)((j+1)*64 + r)*64 + lc];
            }
        }
        __syncthreads();

        // ---- S = Q @ K^T via single-pass TF32 MMA ----
        float acc_s[4][4] = {};
        #pragma unroll
        for (int ks = 0; ks < 8; ks++) {
            uint32_t a0 = QsU[(r0    )*68 + ks*8 + qid    ];
            uint32_t a1 = QsU[(r0 + 8)*68 + ks*8 + qid    ];
            uint32_t a2 = QsU[(r0    )*68 + ks*8 + qid + 4];
            uint32_t a3 = QsU[(r0 + 8)*68 + ks*8 + qid + 4];
            #pragma unroll
            for (int jn = 0; jn < 4; jn++) {
                int col = wn*32 + jn*8;
                uint32_t b0 = KtU[(ks*8 + qid    )*68 + col + grp];
                uint32_t b1 = KtU[(ks*8 + qid + 4)*68 + col + grp];
                mma_tf32(acc_s[jn], a0, a1, a2, a3, b0, b1);
            }
        }
        const bool diag = (j == qt);
        #pragma unroll
        for (int jn = 0; jn < 4; jn++) {
            int c0 = wn*32 + jn*8 + qid*2;
            float v0 = acc_s[jn][0] * 0.125f;
            float v1 = acc_s[jn][1] * 0.125f;
            float v2 = acc_s[jn][2] * 0.125f;
            float v3 = acc_s[jn][3] * 0.125f;
            if (diag) {
                if (c0     > r0    ) v0 = -1e30f;
                if (c0 + 1 > r0    ) v1 = -1e30f;
                if (c0     > r0 + 8) v2 = -1e30f;
                if (c0 + 1 > r0 + 8) v3 = -1e30f;
            }
            Ss[(r0    )*68 + c0    ] = v0;
            Ss[(r0    )*68 + c0 + 1] = v1;
            Ss[(r0 + 8)*68 + c0    ] = v2;
            Ss[(r0 + 8)*68 + c0 + 1] = v3;
        }
        __syncthreads();

        // ---- online softmax: 4 threads/row, shfl combine; P -> tf32 bits ----
        {
            const int row  = tid >> 2;
            const int part = tid & 3;
            const int base = row*68 + part*16;
            float mold = m_sh[row];
            float mx = -1e30f;
            #pragma unroll
            for (int c = 0; c < 16; c++) mx = fmaxf(mx, Ss[base + c]);
            mx = fmaxf(mx, __shfl_xor_sync(0xffffffffu, mx, 1));
            mx = fmaxf(mx, __shfl_xor_sync(0xffffffffu, mx, 2));
            mx = fmaxf(mx, mold);
            float sum = 0.f;
            #pragma unroll
            for (int c = 0; c < 16; c++) {
                float pv = __expf(Ss[base + c] - mx);
                sum += pv;
                SsU[base + c] = f2tf32(pv);
            }
            sum += __shfl_xor_sync(0xffffffffu, sum, 1);
            sum += __shfl_xor_sync(0xffffffffu, sum, 2);
            if (part == 0) {
                float corr = __expf(mold - mx);
                l_sh[row] = l_sh[row]*corr + sum;
                m_sh[row] = mx;
                c_sh[row] = corr;
            }
        }
        __syncthreads();

        // ---- O = O*corr + P @ V via single-pass TF32 MMA ----
        {
            float cA = c_sh[r0], cB = c_sh[r0 + 8];
            #pragma unroll
            for (int jn = 0; jn < 4; jn++) {
                acc_o[jn][0] *= cA; acc_o[jn][1] *= cA;
                acc_o[jn][2] *= cB; acc_o[jn][3] *= cB;
            }
            #pragma unroll
            for (int ks = 0; ks < 8; ks++) {
                uint32_t a0 = SsU[(r0    )*68 + ks*8 + qid    ];
                uint32_t a1 = SsU[(r0 + 8)*68 + ks*8 + qid    ];
                uint32_t a2 = SsU[(r0    )*68 + ks*8 + qid + 4];
                uint32_t a3 = SsU[(r0 + 8)*68 + ks*8 + qid + 4];
                #pragma unroll
                for (int jn = 0; jn < 4; jn++) {
                    int col = wn*32 + jn*8;
                    uint32_t b0 = VsU[(ks*8 + qid    )*68 + col + grp];
                    uint32_t b1 = VsU[(ks*8 + qid + 4)*68 + col + grp];
                    mma_tf32(acc_o[jn], a0, a1, a2, a3, b0, b1);
                }
            }
        }
    }
    __syncthreads();

    // ---- epilogue: MMA C layout, mean over heads via atomics ----
    {
        float invA = 1.f / (l_sh[r0    ] * (float)H_);
        float invB = 1.f / (l_sh[r0 + 8] * (float)H_);
        float* dst = &g_M[((size_t)b*S_ + qt*64)*E_];
        #pragma unroll
        for (int jn = 0; jn < 4; jn++) {
            int c0 = wn*32 + jn*8 + qid*2;
            atomicAdd(&dst[(size_t)(r0    )*E_ + c0    ], acc_o[jn][0]*invA);
            atomicAdd(&dst[(size_t)(r0    )*E_ + c0 + 1], acc_o[jn][1]*invA);
            atomicAdd(&dst[(size_t)(r0 + 8)*E_ + c0    ], acc_o[jn][2]*invB);
            atomicAdd(&dst[(size_t)(r0 + 8)*E_ + c0 + 1], acc_o[jn][3]*invB);
        }
    }
}

// ---------------------------------------------------------------------------
// Final linear: G = g_M[512,512] @ Wf[512,512], single-pass tf32 + prefetch.
__global__ void gemm_g_kernel(const float* __restrict__ Wf) {
    __shared__ uint32_t As[64*36];
    __shared__ uint32_t Bs[32*68];
    const int tid  = threadIdx.x;
    const int lane = tid & 31;
    const int warp = tid >> 5;
    const int wm = warp >> 1, wn = warp & 1;
    const int grp = lane >> 2, qid = lane & 3;
    const int m0 = blockIdx.x * 64, n0 = blockIdx.y * 64;

    const int ar[4] = { (tid      ) >> 3, (tid + 128) >> 3, (tid + 256) >> 3, (tid + 384) >> 3 };
    const int ac[4] = { ((tid      ) & 7)*4, ((tid + 128) & 7)*4, ((tid + 256) & 7)*4, ((tid + 384) & 7)*4 };
    const int br[4] = { (tid      ) >> 4, (tid + 128) >> 4, (tid + 256) >> 4, (tid + 384) >> 4 };
    const int bc[4] = { ((tid      ) & 15)*4, ((tid + 128) & 15)*4, ((tid + 256) & 15)*4, ((tid + 384) & 15)*4 };

    float4 a_pre[4], b_pre[4];
    #pragma unroll
    for (int t = 0; t < 4; t++) {
        a_pre[t] = *(const float4*)&g_M[(size_t)(m0 + ar[t])*512 + ac[t]];
        b_pre[t] = *(const float4*)&Wf[(size_t)br[t]*512 + n0 + bc[t]];
    }

    float acc[2][4][4] = {};

    for (int k0 = 0; k0 < 512; k0 += 32) {
        #pragma unroll
        for (int t = 0; t < 4; t++) {
            float4 av = a_pre[t];
            As[ar[t]*36 + ac[t] + 0] = f2tf32(av.x);
            As[ar[t]*36 + ac[t] + 1] = f2tf32(av.y);
            As[ar[t]*36 + ac[t] + 2] = f2tf32(av.z);
            As[ar[t]*36 + ac[t] + 3] = f2tf32(av.w);
            float4 bvv = b_pre[t];
            Bs[br[t]*68 + bc[t] + 0] = f2tf32(bvv.x);
            Bs[br[t]*68 + bc[t] + 1] = f2tf32(bvv.y);
            Bs[br[t]*68 + bc[t] + 2] = f2tf32(bvv.z);
            Bs[br[t]*68 + bc[t] + 3] = f2tf32(bvv.w);
        }
        if (k0 + 32 < 512) {
            #pragma unroll
            for (int t = 0; t < 4; t++) {
                a_pre[t] = *(const float4*)&g_M[(size_t)(m0 + ar[t])*512 + k0 + 32 + ac[t]];
                b_pre[t] = *(const float4*)&Wf[(size_t)(k0 + 32 + br[t])*512 + n0 + bc[t]];
            }
        }
        __syncthreads();

        #pragma unroll
        for (int ks = 0; ks < 4; ks++) {
            uint32_t a[2][4];
            #pragma unroll
            for (int i = 0; i < 2; i++) {
                int row = wm*32 + i*16;
                a[i][0] = As[(row+grp  )*36 + ks*8 + qid    ];
                a[i][1] = As[(row+grp+8)*36 + ks*8 + qid    ];
                a[i][2] = As[(row+grp  )*36 + ks*8 + qid + 4];
                a[i][3] = As[(row+grp+8)*36 + ks*8 + qid + 4];
            }
            #pragma unroll
            for (int jn = 0; jn < 4; jn++) {
                int col = wn*32 + jn*8;
                uint32_t b0 = Bs[(ks*8 + qid    )*68 + col + grp];
                uint32_t b1 = Bs[(ks*8 + qid + 4)*68 + col + grp];
                mma_tf32(acc[0][jn], a[0][0], a[0][1], a[0][2], a[0][3], b0, b1);
                mma_tf32(acc[1][jn], a[1][0], a[1][1], a[1][2], a[1][3], b0, b1);
            }
        }
        __syncthreads();
    }

    #pragma unroll
    for (int i = 0; i < 2; i++) {
        int row0 = m0 + wm*32 + i*16 + grp;
        #pragma unroll
        for (int jn = 0; jn < 4; jn++) {
            int col0 = n0 + wn*32 + jn*8 + qid*2;
            g_G[(size_t)row0*512     + col0    ] = acc[i][jn][0];
            g_G[(size_t)row0*512     + col0 + 1] = acc[i][jn][1];
            g_G[(size_t)(row0+8)*512 + col0    ] = acc[i][jn][2];
            g_G[(size_t)(row0+8)*512 + col0 + 1] = acc[i][jn][3];
        }
    }
}

// ---------------------------------------------------------------------------
__global__ void ln_kernel(const float* __restrict__ query, const float* __restrict__ bf,
                          const float* __restrict__ lnw, const float* __restrict__ lnb,
                          float* __restrict__ out) {
    const int row  = blockIdx.x;
    const int bb   = row >> 10;
    const int r128 = row & 127;
    const float* g    = g_G + ((size_t)bb*128 + r128)*D_;
    const float* qrow = query + (size_t)row*D_;
    const int tid = threadIdx.x;
    float x[4];
    float sum = 0.f;
    #pragma unroll
    for (int t = 0; t < 4; t++) {
        int c = tid + t*128;
        x[t] = g[c] + bf[c] + qrow[c];
        sum += x[t];
    }
    __shared__ float red[4];
    __shared__ float red2[4];
    #pragma unroll
    for (int off = 16; off; off >>= 1) sum += __shfl_xor_sync(0xffffffffu, sum, off);
    if ((tid & 31) == 0) red[tid >> 5] = sum;
    __syncthreads();
    float mean = (red[0]+red[1]+red[2]+red[3]) * (1.f/512.f);

    float sq = 0.f;
    #pragma unroll
    for (int t = 0; t < 4; t++) { float d = x[t] - mean; sq += d*d; }
    #pragma unroll
    for (int off = 16; off; off >>= 1) sq += __shfl_xor_sync(0xffffffffu, sq, off);
    if ((tid & 31) == 0) red2[tid >> 5] = sq;
    __syncthreads();
    float var_num = red2[0]+red2[1]+red2[2]+red2[3];
    float stdv = sqrtf(var_num * (1.f/511.f));
    float inv  = 1.f / (stdv + 1e-6f);
    #pragma unroll
    for (int t = 0; t < 4; t++) {
        int c = tid + t*128;
        out[(size_t)row*D_ + c] = lnw[c]*(x[t]-mean)*inv + lnb[c];
    }
}

// ---------------------------------------------------------------------------
extern "C" void kernel_launch(void* const* d_in, const int* in_sizes, int n_in,
                              void* d_out, int out_size) {
    const float* query = (const float*)d_in[0];
    const float* key   = (const float*)d_in[1];
    const float* value = (const float*)d_in[2];
    // d_in[3] = mask (tril, handled analytically)
    const float* Wq = (const float*)d_in[4];
    const float* bq = (const float*)d_in[5];
    const float* Wk = (const float*)d_in[6];
    const float* bk = (const float*)d_in[7];
    const float* Wv = (const float*)d_in[8];
    const float* bv = (const float*)d_in[9];
    const float* Wf = (const float*)d_in[10];
    const float* bf = (const float*)d_in[11];
    const float* lnw = (const float*)d_in[12];
    const float* lnb = (const float*)d_in[13];
    float* out = (float*)d_out;

    // attn smem: 4 tiles of 64*68 + 3*64 floats = 70400 B
    const size_t attn_smem = (size_t)(4*64*68 + 3*64) * sizeof(float);
    cudaFuncSetAttribute(attn_kernel, cudaFuncAttributeMaxDynamicSharedMemorySize,
                         (int)attn_smem);

    zero_m_kernel<<<64, 256>>>();
    proj_mma_kernel<<<dim3(BS_/64, 17), 128>>>(query, key, value, Wq, bq, Wk, bk, Wv, bv);
    attn_kernel<<<dim3(S_/64, B_, H_), 256, attn_smem>>>();
    gemm_g_kernel<<<dim3(8, 8), 128>>>(Wf);
    ln_kernel<<<BS_, 128>>>(query, bf, lnw, lnb, out);
}